// round 5
// baseline (speedup 1.0000x reference)
#include <cuda_runtime.h>

// Problem constants (match reference)
#define MASK_P   0.15f
#define MASK_LEN 8
#define B_DIM    64
#define H_DIM    512
#define W_DIM    256
#define HW       (H_DIM * W_DIM)       // 131072 pixels (each = one float4)

#define TPB      128                   // 4 warps/block -> 1024 blocks, single wave

__device__ __forceinline__ void apply(float4& m, float4 r) {
    if (r.x < MASK_P) m.x = 0.f;
    if (r.y < MASK_P) m.y = 0.f;
    if (r.z < MASK_P) m.z = 0.f;
    if (r.w < MASK_P) m.w = 0.f;
}

// ---------------------------------------------------------------------------
// Fused kernel: one thread per (h,w) pixel.
// Prologue: ballot-compacted mask build (~1 time batch + ~10 freq batches of
// 64 actually executed, uniform control flow).
// Body: stream all 64 batches (coalesced float4, streaming cache hints).
// ---------------------------------------------------------------------------
__global__ __launch_bounds__(TPB)
void fused_kernel(const float4* __restrict__ x,
                  const float4* __restrict__ time_rand,   // [B,8,W] of float4
                  const float4* __restrict__ freq_rand,   // [B,H,8] of float4
                  const int*    __restrict__ time_starts,
                  const int*    __restrict__ freq_starts,
                  float4*       __restrict__ out)
{
    const int pix = blockIdx.x * TPB + threadIdx.x;
    const int w   = pix & (W_DIM - 1);
    const int h   = pix >> 8;                 // block-uniform (128 | 256)

    __shared__ int s_ts[B_DIM];
    __shared__ int s_fs[B_DIM];
    __shared__ unsigned s_tact[2];            // 64-bit time-active batch mask

    if (threadIdx.x < B_DIM) {
        s_ts[threadIdx.x] = time_starts[threadIdx.x];
        s_fs[threadIdx.x] = freq_starts[threadIdx.x];
    }
    __syncthreads();

    const int warp = threadIdx.x >> 5;
    const int lane = threadIdx.x & 31;

    // Which batches' time windows cover this row h (h uniform in block).
    if (warp < 2) {
        int b = warp * 32 + lane;
        unsigned flag = ((unsigned)(h - s_ts[b]) < (unsigned)MASK_LEN) ? 1u : 0u;
        unsigned bal = __ballot_sync(0xFFFFFFFFu, flag);
        if (lane == 0) s_tact[warp] = bal;
    }
    __syncthreads();

    float4 m = make_float4(1.f, 1.f, 1.f, 1.f);

    // ---- time contributions: iterate only active bits (uniform) ----
    #pragma unroll
    for (int half = 0; half < 2; ++half) {
        unsigned act = s_tact[half];
        while (act) {
            int b = half * 32 + (__ffs(act) - 1);
            act &= act - 1;
            int lt = h - s_ts[b];             // in [0, 8)
            float4 tr = __ldg(&time_rand[(b * MASK_LEN + lt) * W_DIM + w]);
            apply(m, tr);
        }
    }

    // ---- freq candidates: b touches this warp iff fs[b] in [w0-7, w0+31] ----
    const int w0 = w & ~31;
    unsigned f0 = ((unsigned)(s_fs[lane]      - w0 + (MASK_LEN - 1)) < (unsigned)(32 + MASK_LEN - 1)) ? 1u : 0u;
    unsigned f1 = ((unsigned)(s_fs[lane + 32] - w0 + (MASK_LEN - 1)) < (unsigned)(32 + MASK_LEN - 1)) ? 1u : 0u;
    unsigned c0 = __ballot_sync(0xFFFFFFFFu, f0);
    unsigned c1 = __ballot_sync(0xFFFFFFFFu, f1);

    while (c0) {
        int b = __ffs(c0) - 1;
        c0 &= c0 - 1;
        int lf = w - s_fs[b];
        if ((unsigned)lf < (unsigned)MASK_LEN) {   // short arm -> predicated
            float4 fr = __ldg(&freq_rand[(b * H_DIM + h) * MASK_LEN + lf]);
            apply(m, fr);
        }
    }
    while (c1) {
        int b = 32 + (__ffs(c1) - 1);
        c1 &= c1 - 1;
        int lf = w - s_fs[b];
        if ((unsigned)lf < (unsigned)MASK_LEN) {
            float4 fr = __ldg(&freq_rand[(b * H_DIM + h) * MASK_LEN + lf]);
            apply(m, fr);
        }
    }

    // ---- stream all 64 batches through this pixel ----
    const float4* __restrict__ xp = x   + pix;
    float4*       __restrict__ op = out + pix;

    #pragma unroll 16
    for (int b = 0; b < B_DIM; ++b) {
        float4 v = __ldcs(&xp[b * HW]);       // touched once: evict-first
        v.x *= m.x; v.y *= m.y; v.z *= m.z; v.w *= m.w;
        __stcs(&op[b * HW], v);
    }
}

extern "C" void kernel_launch(void* const* d_in, const int* in_sizes, int n_in,
                              void* d_out, int out_size)
{
    const float4* x    = (const float4*)d_in[0];
    const float4* tr   = (const float4*)d_in[1];
    const float4* fr   = (const float4*)d_in[2];
    const int*    ts   = (const int*)d_in[3];
    const int*    fs   = (const int*)d_in[4];
    float4*       out  = (float4*)d_out;

    fused_kernel<<<HW / TPB, TPB>>>(x, tr, fr, ts, fs, out);   // 1024 x 128
}

// round 6
// speedup vs baseline: 1.2716x; 1.2716x over previous
#include <cuda_runtime.h>

// Problem constants (match reference)
#define MASK_P   0.15f
#define MASK_LEN 8
#define B_DIM    64
#define H_DIM    512
#define W_DIM    256
#define HW       (H_DIM * W_DIM)       // 131072 pixels (each = one float4)

#define TPB      256
#define BSPLIT   4                     // batch chunks (grid.y)
#define B_PER_T  (B_DIM / BSPLIT)      // 16 batches streamed per thread

__device__ __forceinline__ void apply(float4& m, float4 r) {
    if (r.x < MASK_P) m.x = 0.f;
    if (r.y < MASK_P) m.y = 0.f;
    if (r.z < MASK_P) m.z = 0.f;
    if (r.w < MASK_P) m.w = 0.f;
}

// ---------------------------------------------------------------------------
// Fused kernel, R3-stream grid shape (2048 x 256 -> occ ~80%, DRAM ~72%)
// with R4's ballot-compacted mask prologue (cheap, uniform control flow).
// Each thread: build 4-channel mask for its pixel, stream 16 batches.
// ---------------------------------------------------------------------------
__global__ __launch_bounds__(TPB)
void fused_kernel(const float4* __restrict__ x,
                  const float4* __restrict__ time_rand,   // [B,8,W] of float4
                  const float4* __restrict__ freq_rand,   // [B,H,8] of float4
                  const int*    __restrict__ time_starts,
                  const int*    __restrict__ freq_starts,
                  float4*       __restrict__ out)
{
    const int pix = blockIdx.x * TPB + threadIdx.x;
    const int w   = pix & (W_DIM - 1);
    const int h   = pix >> 8;                 // block-uniform (256 = one row)

    __shared__ int s_ts[B_DIM];
    __shared__ int s_fs[B_DIM];
    __shared__ unsigned s_tact[2];            // 64-bit time-active batch mask

    if (threadIdx.x < B_DIM) {
        s_ts[threadIdx.x] = time_starts[threadIdx.x];
        s_fs[threadIdx.x] = freq_starts[threadIdx.x];
    }
    __syncthreads();

    const int warp = threadIdx.x >> 5;
    const int lane = threadIdx.x & 31;

    // Which batches' time windows cover this row h (h uniform in block).
    if (warp < 2) {
        int b = warp * 32 + lane;
        unsigned flag = ((unsigned)(h - s_ts[b]) < (unsigned)MASK_LEN) ? 1u : 0u;
        unsigned bal = __ballot_sync(0xFFFFFFFFu, flag);
        if (lane == 0) s_tact[warp] = bal;
    }
    __syncthreads();

    float4 m = make_float4(1.f, 1.f, 1.f, 1.f);

    // ---- time contributions: iterate only active bits (uniform) ----
    #pragma unroll
    for (int half = 0; half < 2; ++half) {
        unsigned act = s_tact[half];
        while (act) {
            int b = half * 32 + (__ffs(act) - 1);
            act &= act - 1;
            int lt = h - s_ts[b];             // in [0, 8)
            float4 tr = __ldg(&time_rand[(b * MASK_LEN + lt) * W_DIM + w]);
            apply(m, tr);
        }
    }

    // ---- freq candidates: b touches this warp iff fs[b] in [w0-7, w0+31] ----
    const int w0 = w & ~31;
    unsigned f0 = ((unsigned)(s_fs[lane]      - w0 + (MASK_LEN - 1)) < (unsigned)(32 + MASK_LEN - 1)) ? 1u : 0u;
    unsigned f1 = ((unsigned)(s_fs[lane + 32] - w0 + (MASK_LEN - 1)) < (unsigned)(32 + MASK_LEN - 1)) ? 1u : 0u;
    unsigned c0 = __ballot_sync(0xFFFFFFFFu, f0);
    unsigned c1 = __ballot_sync(0xFFFFFFFFu, f1);

    while (c0) {
        int b = __ffs(c0) - 1;
        c0 &= c0 - 1;
        int lf = w - s_fs[b];
        if ((unsigned)lf < (unsigned)MASK_LEN) {   // short arm -> predicated
            float4 fr = __ldg(&freq_rand[(b * H_DIM + h) * MASK_LEN + lf]);
            apply(m, fr);
        }
    }
    while (c1) {
        int b = 32 + (__ffs(c1) - 1);
        c1 &= c1 - 1;
        int lf = w - s_fs[b];
        if ((unsigned)lf < (unsigned)MASK_LEN) {
            float4 fr = __ldg(&freq_rand[(b * H_DIM + h) * MASK_LEN + lf]);
            apply(m, fr);
        }
    }

    // ---- stream this chunk's 16 batches through the pixel (R3 shape) ----
    const int b0 = blockIdx.y * B_PER_T;
    const float4* __restrict__ xp = x   + (size_t)b0 * HW + pix;
    float4*       __restrict__ op = out + (size_t)b0 * HW + pix;

    #pragma unroll
    for (int b = 0; b < B_PER_T; ++b) {
        float4 v = xp[b * HW];
        v.x *= m.x; v.y *= m.y; v.z *= m.z; v.w *= m.w;
        op[b * HW] = v;
    }
}

extern "C" void kernel_launch(void* const* d_in, const int* in_sizes, int n_in,
                              void* d_out, int out_size)
{
    const float4* x    = (const float4*)d_in[0];
    const float4* tr   = (const float4*)d_in[1];
    const float4* fr   = (const float4*)d_in[2];
    const int*    ts   = (const int*)d_in[3];
    const int*    fs   = (const int*)d_in[4];
    float4*       out  = (float4*)d_out;

    dim3 grid(HW / TPB, BSPLIT);              // 512 x 4 = 2048 blocks
    fused_kernel<<<grid, TPB>>>(x, tr, fr, ts, fs, out);
}

// round 7
// speedup vs baseline: 1.3147x; 1.0339x over previous
#include <cuda_runtime.h>

// Problem constants (match reference)
#define MASK_P   0.15f
#define MASK_LEN 8
#define B_DIM    64
#define H_DIM    512
#define W_DIM    256
#define HW       (H_DIM * W_DIM)       // 131072 pixels (each = one float4)

#define TPB      256
#define BSPLIT   4                     // batch chunks (grid.y)
#define B_PER_T  (B_DIM / BSPLIT)      // 16 batches streamed per thread

// ---------------------------------------------------------------------------
// Fused kernel. Block = one h row x one batch chunk.
// Prologue (cooperative):
//   - freq mask: 64 threads, one batch each, atomicOr 4-bit channel masks
//     into s_fbits[col] for the batch's 8-wide window.
//   - time mask: ballot-compacted active-batch loop (expected ~1 batch).
// Body: stream 16 batches of coalesced float4 (R3 shape: 72% DRAM measured).
// ---------------------------------------------------------------------------
__global__ __launch_bounds__(TPB, 8)
void fused_kernel(const float4* __restrict__ x,
                  const float4* __restrict__ time_rand,   // [B,8,W] of float4
                  const float4* __restrict__ freq_rand,   // [B,H,8] of float4
                  const int*    __restrict__ time_starts,
                  const int*    __restrict__ freq_starts,
                  float4*       __restrict__ out)
{
    const int pix = blockIdx.x * TPB + threadIdx.x;
    const int w   = pix & (W_DIM - 1);
    const int h   = pix >> 8;                 // block-uniform (256 = one row)

    __shared__ int      s_ts[B_DIM];
    __shared__ unsigned s_tact[2];            // 64-bit time-active batch mask
    __shared__ unsigned s_fbits[W_DIM];       // per-column freq channel-zero bits

    s_fbits[threadIdx.x] = 0u;
    if (threadIdx.x < B_DIM) {
        s_ts[threadIdx.x] = time_starts[threadIdx.x];
    }
    __syncthreads();

    const int warp = threadIdx.x >> 5;
    const int lane = threadIdx.x & 31;

    // Warps 0-1 (threads 0..63): ballot time-active batches, then each of the
    // 64 threads processes ONE batch's freq window cooperatively.
    if (warp < 2) {
        const int b = threadIdx.x;            // batch id, 0..63

        // time-active ballot (h uniform across block)
        unsigned flag = ((unsigned)(h - s_ts[b]) < (unsigned)MASK_LEN) ? 1u : 0u;
        unsigned bal = __ballot_sync(0xFFFFFFFFu, flag);
        if (lane == 0) s_tact[warp] = bal;

        // freq window for batch b: cols [fs, fs+8), 8 contiguous float4 loads
        const int fs = freq_starts[b];
        const float4* __restrict__ fp = freq_rand + ((size_t)b * H_DIM + h) * MASK_LEN;
        #pragma unroll
        for (int lf = 0; lf < MASK_LEN; ++lf) {
            float4 fr = __ldg(&fp[lf]);
            unsigned bits = (fr.x < MASK_P ? 1u : 0u)
                          | (fr.y < MASK_P ? 2u : 0u)
                          | (fr.z < MASK_P ? 4u : 0u)
                          | (fr.w < MASK_P ? 8u : 0u);
            if (bits) atomicOr(&s_fbits[fs + lf], bits);
        }
    }
    __syncthreads();

    // Combine freq bits into the 4-channel multiplier for this column.
    const unsigned fb = s_fbits[w];
    float4 m;
    m.x = (fb & 1u) ? 0.f : 1.f;
    m.y = (fb & 2u) ? 0.f : 1.f;
    m.z = (fb & 4u) ? 0.f : 1.f;
    m.w = (fb & 8u) ? 0.f : 1.f;

    // Time contributions: iterate only active bits (uniform control flow).
    #pragma unroll
    for (int half = 0; half < 2; ++half) {
        unsigned act = s_tact[half];
        while (act) {
            int b = half * 32 + (__ffs(act) - 1);
            act &= act - 1;
            int lt = h - s_ts[b];             // in [0, 8)
            float4 tr = __ldg(&time_rand[(b * MASK_LEN + lt) * W_DIM + w]);
            if (tr.x < MASK_P) m.x = 0.f;
            if (tr.y < MASK_P) m.y = 0.f;
            if (tr.z < MASK_P) m.z = 0.f;
            if (tr.w < MASK_P) m.w = 0.f;
        }
    }

    // ---- stream this chunk's 16 batches through the pixel (R3 shape) ----
    const int b0 = blockIdx.y * B_PER_T;
    const float4* __restrict__ xp = x   + (size_t)b0 * HW + pix;
    float4*       __restrict__ op = out + (size_t)b0 * HW + pix;

    #pragma unroll
    for (int b = 0; b < B_PER_T; ++b) {
        float4 v = xp[b * HW];
        v.x *= m.x; v.y *= m.y; v.z *= m.z; v.w *= m.w;
        op[b * HW] = v;
    }
}

extern "C" void kernel_launch(void* const* d_in, const int* in_sizes, int n_in,
                              void* d_out, int out_size)
{
    const float4* x    = (const float4*)d_in[0];
    const float4* tr   = (const float4*)d_in[1];
    const float4* fr   = (const float4*)d_in[2];
    const int*    ts   = (const int*)d_in[3];
    const int*    fs   = (const int*)d_in[4];
    float4*       out  = (float4*)d_out;

    dim3 grid(HW / TPB, BSPLIT);              // 512 x 4 = 2048 blocks
    fused_kernel<<<grid, TPB>>>(x, tr, fr, ts, fs, out);
}

// round 8
// speedup vs baseline: 1.3220x; 1.0056x over previous
#include <cuda_runtime.h>

// Problem constants (match reference)
#define MASK_P   0.15f
#define MASK_LEN 8
#define B_DIM    64
#define H_DIM    512
#define W_DIM    256
#define HW       (H_DIM * W_DIM)       // 131072 pixels (each = one float4)

#define TPB      256
#define BSPLIT   2                     // batch chunks (grid.y): halves prologue count
#define B_PER_T  (B_DIM / BSPLIT)      // 32 batches streamed per thread

// ---------------------------------------------------------------------------
// Fused kernel. Block = one h row x one batch chunk.
// Prologue (cooperative, measured cheap in R7):
//   - freq mask: threads 0..63 take one batch each, atomicOr 4-bit channel
//     masks into s_fbits[col] over the batch's 8-wide window.
//   - time mask: ballot-compacted active-batch loop (expected ~1 batch).
// Body: stream 32 batches of coalesced float4.
// 1024 blocks -> 6.9/SM: fully resident in ONE wave, ~1% imbalance.
// ---------------------------------------------------------------------------
__global__ __launch_bounds__(TPB, 8)
void fused_kernel(const float4* __restrict__ x,
                  const float4* __restrict__ time_rand,   // [B,8,W] of float4
                  const float4* __restrict__ freq_rand,   // [B,H,8] of float4
                  const int*    __restrict__ time_starts,
                  const int*    __restrict__ freq_starts,
                  float4*       __restrict__ out)
{
    const int pix = blockIdx.x * TPB + threadIdx.x;
    const int w   = pix & (W_DIM - 1);
    const int h   = pix >> 8;                 // block-uniform (256 = one row)

    __shared__ int      s_ts[B_DIM];
    __shared__ unsigned s_tact[2];            // 64-bit time-active batch mask
    __shared__ unsigned s_fbits[W_DIM];       // per-column freq channel-zero bits

    s_fbits[threadIdx.x] = 0u;
    if (threadIdx.x < B_DIM) {
        s_ts[threadIdx.x] = time_starts[threadIdx.x];
    }
    __syncthreads();

    const int warp = threadIdx.x >> 5;
    const int lane = threadIdx.x & 31;

    // Warps 0-1 (threads 0..63): ballot time-active batches, then each of the
    // 64 threads processes ONE batch's freq window cooperatively.
    if (warp < 2) {
        const int b = threadIdx.x;            // batch id, 0..63

        // time-active ballot (h uniform across block)
        unsigned flag = ((unsigned)(h - s_ts[b]) < (unsigned)MASK_LEN) ? 1u : 0u;
        unsigned bal = __ballot_sync(0xFFFFFFFFu, flag);
        if (lane == 0) s_tact[warp] = bal;

        // freq window for batch b: cols [fs, fs+8), 8 contiguous float4 loads
        const int fs = freq_starts[b];
        const float4* __restrict__ fp = freq_rand + ((size_t)b * H_DIM + h) * MASK_LEN;
        #pragma unroll
        for (int lf = 0; lf < MASK_LEN; ++lf) {
            float4 fr = __ldg(&fp[lf]);
            unsigned bits = (fr.x < MASK_P ? 1u : 0u)
                          | (fr.y < MASK_P ? 2u : 0u)
                          | (fr.z < MASK_P ? 4u : 0u)
                          | (fr.w < MASK_P ? 8u : 0u);
            if (bits) atomicOr(&s_fbits[fs + lf], bits);
        }
    }
    __syncthreads();

    // Combine freq bits into the 4-channel multiplier for this column.
    const unsigned fb = s_fbits[w];
    float4 m;
    m.x = (fb & 1u) ? 0.f : 1.f;
    m.y = (fb & 2u) ? 0.f : 1.f;
    m.z = (fb & 4u) ? 0.f : 1.f;
    m.w = (fb & 8u) ? 0.f : 1.f;

    // Time contributions: iterate only active bits (uniform control flow).
    #pragma unroll
    for (int half = 0; half < 2; ++half) {
        unsigned act = s_tact[half];
        while (act) {
            int b = half * 32 + (__ffs(act) - 1);
            act &= act - 1;
            int lt = h - s_ts[b];             // in [0, 8)
            float4 tr = __ldg(&time_rand[(b * MASK_LEN + lt) * W_DIM + w]);
            if (tr.x < MASK_P) m.x = 0.f;
            if (tr.y < MASK_P) m.y = 0.f;
            if (tr.z < MASK_P) m.z = 0.f;
            if (tr.w < MASK_P) m.w = 0.f;
        }
    }

    // ---- stream this chunk's 32 batches through the pixel ----
    const int b0 = blockIdx.y * B_PER_T;
    const float4* __restrict__ xp = x   + (size_t)b0 * HW + pix;
    float4*       __restrict__ op = out + (size_t)b0 * HW + pix;

    #pragma unroll 16
    for (int b = 0; b < B_PER_T; ++b) {
        float4 v = xp[b * HW];
        v.x *= m.x; v.y *= m.y; v.z *= m.z; v.w *= m.w;
        op[b * HW] = v;
    }
}

extern "C" void kernel_launch(void* const* d_in, const int* in_sizes, int n_in,
                              void* d_out, int out_size)
{
    const float4* x    = (const float4*)d_in[0];
    const float4* tr   = (const float4*)d_in[1];
    const float4* fr   = (const float4*)d_in[2];
    const int*    ts   = (const int*)d_in[3];
    const int*    fs   = (const int*)d_in[4];
    float4*       out  = (float4*)d_out;

    dim3 grid(HW / TPB, BSPLIT);              // 512 x 2 = 1024 blocks
    fused_kernel<<<grid, TPB>>>(x, tr, fr, ts, fs, out);
}

// round 9
// speedup vs baseline: 1.3277x; 1.0044x over previous
#include <cuda_runtime.h>

// Problem constants (match reference)
#define MASK_P   0.15f
#define MASK_LEN 8
#define B_DIM    64
#define H_DIM    512
#define W_DIM    256
#define HW       (H_DIM * W_DIM)       // 131072 pixels (each = one float4)

#define TPB      256
#define BSPLIT   2                     // batch chunks (grid.y)
#define B_PER_T  (B_DIM / BSPLIT)      // 32 batches streamed per thread

// ---------------------------------------------------------------------------
// Fused kernel. Block = one h row x one batch chunk.
// Prologue (fully distributed):
//   - freq mask: 512 (batch, offset) window loads spread as exactly 2 per
//     thread (coalesced 128B per batch), atomicOr 4-bit channel masks into
//     s_fbits[col]. Every warp issues loads -> short, uniform barrier tail.
//   - time mask: ballot over direct __ldg of time_starts (no smem staging).
// Body: stream 32 batches of coalesced float4 (unchanged, measured 68% DRAM).
// ---------------------------------------------------------------------------
__global__ __launch_bounds__(TPB, 8)
void fused_kernel(const float4* __restrict__ x,
                  const float4* __restrict__ time_rand,   // [B,8,W] of float4
                  const float4* __restrict__ freq_rand,   // [B,H,8] of float4
                  const int*    __restrict__ time_starts,
                  const int*    __restrict__ freq_starts,
                  float4*       __restrict__ out)
{
    const int tid = threadIdx.x;
    const int pix = blockIdx.x * TPB + tid;
    const int w   = pix & (W_DIM - 1);
    const int h   = pix >> 8;                 // block-uniform (256 = one row)

    __shared__ unsigned s_tact[2];            // 64-bit time-active batch mask
    __shared__ unsigned s_fbits[W_DIM];       // per-column freq channel-zero bits

    s_fbits[tid] = 0u;
    __syncthreads();                          // zero-init before atomics

    const int warp = tid >> 5;
    const int lane = tid & 31;

    // Time-active ballot (h uniform in block; starts read straight from L1/L2).
    if (warp < 2) {
        unsigned flag =
            ((unsigned)(h - __ldg(&time_starts[tid])) < (unsigned)MASK_LEN) ? 1u : 0u;
        unsigned bal = __ballot_sync(0xFFFFFFFFu, flag);
        if (lane == 0) s_tact[warp] = bal;
    }

    // Freq windows: 512 (b, lf) pairs distributed 2-per-thread.
    // p = tid and tid+256;  b = p>>3, lf = p&7  -> 8 consecutive threads
    // cover one batch's contiguous 128B window (coalesced).
    #pragma unroll
    for (int rep = 0; rep < 2; ++rep) {
        const int p  = tid + rep * TPB;
        const int b  = p >> 3;
        const int lf = p & 7;
        const int fs = __ldg(&freq_starts[b]);
        float4 fr = __ldg(&freq_rand[((size_t)b * H_DIM + h) * MASK_LEN + lf]);
        unsigned bits = (fr.x < MASK_P ? 1u : 0u)
                      | (fr.y < MASK_P ? 2u : 0u)
                      | (fr.z < MASK_P ? 4u : 0u)
                      | (fr.w < MASK_P ? 8u : 0u);
        if (bits) atomicOr(&s_fbits[fs + lf], bits);
    }
    __syncthreads();                          // fbits + tact ready

    // Combine freq bits into the 4-channel multiplier for this column.
    const unsigned fb = s_fbits[w];
    float4 m;
    m.x = (fb & 1u) ? 0.f : 1.f;
    m.y = (fb & 2u) ? 0.f : 1.f;
    m.z = (fb & 4u) ? 0.f : 1.f;
    m.w = (fb & 8u) ? 0.f : 1.f;

    // Time contributions: iterate only active bits (expected ~1 of 64).
    #pragma unroll
    for (int half = 0; half < 2; ++half) {
        unsigned act = s_tact[half];
        while (act) {
            int b = half * 32 + (__ffs(act) - 1);
            act &= act - 1;
            int lt = h - __ldg(&time_starts[b]);     // in [0, 8)
            float4 tr = __ldg(&time_rand[(b * MASK_LEN + lt) * W_DIM + w]);
            if (tr.x < MASK_P) m.x = 0.f;
            if (tr.y < MASK_P) m.y = 0.f;
            if (tr.z < MASK_P) m.z = 0.f;
            if (tr.w < MASK_P) m.w = 0.f;
        }
    }

    // ---- stream this chunk's 32 batches through the pixel (R8 shape) ----
    const int b0 = blockIdx.y * B_PER_T;
    const float4* __restrict__ xp = x   + (size_t)b0 * HW + pix;
    float4*       __restrict__ op = out + (size_t)b0 * HW + pix;

    #pragma unroll 16
    for (int b = 0; b < B_PER_T; ++b) {
        float4 v = xp[b * HW];
        v.x *= m.x; v.y *= m.y; v.z *= m.z; v.w *= m.w;
        op[b * HW] = v;
    }
}

extern "C" void kernel_launch(void* const* d_in, const int* in_sizes, int n_in,
                              void* d_out, int out_size)
{
    const float4* x    = (const float4*)d_in[0];
    const float4* tr   = (const float4*)d_in[1];
    const float4* fr   = (const float4*)d_in[2];
    const int*    ts   = (const int*)d_in[3];
    const int*    fs   = (const int*)d_in[4];
    float4*       out  = (float4*)d_out;

    dim3 grid(HW / TPB, BSPLIT);              // 512 x 2 = 1024 blocks
    fused_kernel<<<grid, TPB>>>(x, tr, fr, ts, fs, out);
}

// round 10
// speedup vs baseline: 1.4348x; 1.0806x over previous
#include <cuda_runtime.h>

// Problem constants (match reference)
#define MASK_P   0.15f
#define MASK_LEN 8
#define B_DIM    64
#define H_DIM    512
#define W_DIM    256
#define HW       (H_DIM * W_DIM)       // 131072 pixels (each = one float4)

#define TPB      256
#define BSPLIT   2                     // batch chunks (grid.y)
#define B_PER_T  (B_DIM / BSPLIT)      // 32 batches streamed per thread

// ---------------------------------------------------------------------------
// Fused kernel (R9 structure, byte-identical except stream cache hints).
// Prologue:
//   - freq mask: 512 (batch, offset) window loads spread 2-per-thread,
//     atomicOr 4-bit channel masks into s_fbits[col].
//   - time mask: ballot over direct __ldg of time_starts.
// Body: stream 32 batches of coalesced float4 with .cs (evict-first) hints —
// x/out are single-touch; keep them from churning L2 write-allocate state.
// ---------------------------------------------------------------------------
__global__ __launch_bounds__(TPB, 8)
void fused_kernel(const float4* __restrict__ x,
                  const float4* __restrict__ time_rand,   // [B,8,W] of float4
                  const float4* __restrict__ freq_rand,   // [B,H,8] of float4
                  const int*    __restrict__ time_starts,
                  const int*    __restrict__ freq_starts,
                  float4*       __restrict__ out)
{
    const int tid = threadIdx.x;
    const int pix = blockIdx.x * TPB + tid;
    const int w   = pix & (W_DIM - 1);
    const int h   = pix >> 8;                 // block-uniform (256 = one row)

    __shared__ unsigned s_tact[2];            // 64-bit time-active batch mask
    __shared__ unsigned s_fbits[W_DIM];       // per-column freq channel-zero bits

    s_fbits[tid] = 0u;
    __syncthreads();                          // zero-init before atomics

    const int warp = tid >> 5;
    const int lane = tid & 31;

    // Time-active ballot (h uniform in block).
    if (warp < 2) {
        unsigned flag =
            ((unsigned)(h - __ldg(&time_starts[tid])) < (unsigned)MASK_LEN) ? 1u : 0u;
        unsigned bal = __ballot_sync(0xFFFFFFFFu, flag);
        if (lane == 0) s_tact[warp] = bal;
    }

    // Freq windows: 512 (b, lf) pairs distributed 2-per-thread (coalesced).
    #pragma unroll
    for (int rep = 0; rep < 2; ++rep) {
        const int p  = tid + rep * TPB;
        const int b  = p >> 3;
        const int lf = p & 7;
        const int fs = __ldg(&freq_starts[b]);
        float4 fr = __ldg(&freq_rand[((size_t)b * H_DIM + h) * MASK_LEN + lf]);
        unsigned bits = (fr.x < MASK_P ? 1u : 0u)
                      | (fr.y < MASK_P ? 2u : 0u)
                      | (fr.z < MASK_P ? 4u : 0u)
                      | (fr.w < MASK_P ? 8u : 0u);
        if (bits) atomicOr(&s_fbits[fs + lf], bits);
    }
    __syncthreads();                          // fbits + tact ready

    // Combine freq bits into the 4-channel multiplier for this column.
    const unsigned fb = s_fbits[w];
    float4 m;
    m.x = (fb & 1u) ? 0.f : 1.f;
    m.y = (fb & 2u) ? 0.f : 1.f;
    m.z = (fb & 4u) ? 0.f : 1.f;
    m.w = (fb & 8u) ? 0.f : 1.f;

    // Time contributions: iterate only active bits (expected ~1 of 64).
    #pragma unroll
    for (int half = 0; half < 2; ++half) {
        unsigned act = s_tact[half];
        while (act) {
            int b = half * 32 + (__ffs(act) - 1);
            act &= act - 1;
            int lt = h - __ldg(&time_starts[b]);     // in [0, 8)
            float4 tr = __ldg(&time_rand[(b * MASK_LEN + lt) * W_DIM + w]);
            if (tr.x < MASK_P) m.x = 0.f;
            if (tr.y < MASK_P) m.y = 0.f;
            if (tr.z < MASK_P) m.z = 0.f;
            if (tr.w < MASK_P) m.w = 0.f;
        }
    }

    // ---- stream this chunk's 32 batches (single-touch: evict-first) ----
    const int b0 = blockIdx.y * B_PER_T;
    const float4* __restrict__ xp = x   + (size_t)b0 * HW + pix;
    float4*       __restrict__ op = out + (size_t)b0 * HW + pix;

    #pragma unroll 16
    for (int b = 0; b < B_PER_T; ++b) {
        float4 v = __ldcs(&xp[b * HW]);
        v.x *= m.x; v.y *= m.y; v.z *= m.z; v.w *= m.w;
        __stcs(&op[b * HW], v);
    }
}

extern "C" void kernel_launch(void* const* d_in, const int* in_sizes, int n_in,
                              void* d_out, int out_size)
{
    const float4* x    = (const float4*)d_in[0];
    const float4* tr   = (const float4*)d_in[1];
    const float4* fr   = (const float4*)d_in[2];
    const int*    ts   = (const int*)d_in[3];
    const int*    fs   = (const int*)d_in[4];
    float4*       out  = (float4*)d_out;

    dim3 grid(HW / TPB, BSPLIT);              // 512 x 2 = 1024 blocks
    fused_kernel<<<grid, TPB>>>(x, tr, fr, ts, fs, out);
}